// round 11
// baseline (speedup 1.0000x reference)
#include <cuda_runtime.h>
#include <math.h>

#define B_    16
#define H_    512
#define W_    512
#define NPIX  (B_ * H_ * W_)
#define BIGF  100000000.0f
#define SENTI (1 << 28)
#define MAIN_BX 64
#define MAIN_TOTAL (MAIN_BX * B_)

// ---------------- scratch (device globals; no allocation) ----------------
__device__ unsigned short g_d[NPIX];            // vertical distance (0..511; >511 => BIG)
__device__ unsigned int   g_zmask[NPIX / 32];   // row-major zero bitmask of targets
__device__ float  g_rowsf[B_ * W_];             // f (squared) at h==b rows
__device__ int    g_maxf[B_];                   // per-batch max f (float bits)
__device__ double g_acc[4];                     // [wmse, sum_p, sum_t, sum_pt]
__device__ unsigned int g_done;

// ================= K0: build zero bitmask (bandwidth-optimal) =================
// Thread = one 32-pixel word: 8 contiguous float4 loads, 32 predicated ORs.
__global__ void __launch_bounds__(256)
k_mask(const float4* __restrict__ t4) {
    const int wi = blockIdx.x * 256 + threadIdx.x;   // word index 0..131071
    if (blockIdx.x == 0) {
        if (threadIdx.x < B_) g_maxf[threadIdx.x] = 0;
        if (threadIdx.x < 4)  g_acc[threadIdx.x]  = 0.0;
        if (threadIdx.x == 31) g_done = 0u;
    }
    const float4* p = t4 + (size_t)wi * 8;
    float4 v[8];
    #pragma unroll
    for (int i = 0; i < 8; ++i) v[i] = p[i];
    unsigned mword = 0u;
    #pragma unroll
    for (int i = 0; i < 8; ++i) {
        if (v[i].x == 0.0f) mword |= 1u << (4 * i + 0);
        if (v[i].y == 0.0f) mword |= 1u << (4 * i + 1);
        if (v[i].z == 0.0f) mword |= 1u << (4 * i + 2);
        if (v[i].w == 0.0f) mword |= 1u << (4 * i + 3);
    }
    g_zmask[wi] = mword;
}

// ================= K1: vertical distances from bitmask (L2-resident) =================
// grid (16,16): 32-col group x batch. Block 512 = 16 warps; warp w: rows [32w,32w+32).
__global__ void __launch_bounds__(512, 2)
k_vert() {
    __shared__ int s_first[16][32];
    __shared__ int s_last[16][32];
    __shared__ unsigned short sdn[32][512];   // backward distances

    const int lane = threadIdx.x & 31;
    const int w    = threadIdx.x >> 5;
    const int cg   = blockIdx.x;
    const int b    = blockIdx.y;
    const int col  = cg * 32 + lane;
    const int r0   = w * 32;

    // lane reads the zmask word of row (r0+lane) for this column group
    unsigned x = g_zmask[((size_t)b * H_ + r0 + lane) * (W_ / 32) + cg];

    // 32x32 bit-matrix transpose via shfl butterfly:
    // after: bit i of lane l = zero at row (r0+i), col (32cg+l)
    #pragma unroll
    for (int d = 16; d > 0; d >>= 1) {
        const unsigned m = (d == 16) ? 0x0000FFFFu :
                           (d == 8)  ? 0x00FF00FFu :
                           (d == 4)  ? 0x0F0F0F0Fu :
                           (d == 2)  ? 0x33333333u : 0x55555555u;
        unsigned y = __shfl_xor_sync(0xffffffffu, x, d);
        x = (lane & d) ? ((x & ~m) | ((y & ~m) >> d))
                       : ((x &  m) | ((y &  m) << d));
    }
    const unsigned colmask = x;

    s_last[w][lane]  = colmask ? (r0 + 31 - __clz(colmask)) : -SENTI;
    s_first[w][lane] = colmask ? (r0 + __ffs(colmask) - 1)  :  SENTI;
    __syncthreads();

    int lastAbove = -SENTI, nextBelow = SENTI;
    #pragma unroll
    for (int k = 0; k < 16; ++k) {
        int ll = s_last[k][lane];
        int ff = s_first[k][lane];
        if (k < w) lastAbove = max(lastAbove, ll);
        if (k > w) nextBelow = min(nextBelow, ff);
    }

    // backward pass -> shared
    {
        int d = min(nextBelow - (r0 + 32), 0x7FFE);
        #pragma unroll
        for (int i = 31; i >= 0; --i) {
            d = ((colmask >> i) & 1u) ? 0 : d + 1;
            sdn[i][threadIdx.x] = (unsigned short)d;
        }
    }
    // forward pass + emit
    unsigned short* gbase = g_d + (size_t)b * H_ * W_ + col;
    {
        int du = min((r0 - 1) - lastAbove, 0x7FFE);
        #pragma unroll
        for (int i = 0; i < 32; ++i) {
            du = ((colmask >> i) & 1u) ? 0 : du + 1;
            int dm = min(du, (int)sdn[i][threadIdx.x]);
            gbase[(size_t)(r0 + i) * W_] = (unsigned short)min(dm, 0x7FFF);
        }
    }
}

// ================= K2: row transform (warp per row) =================
// grid 1024, block 256 (8 warps -> 8 rows per block).
__global__ void __launch_bounds__(256)
k_row() {
    __shared__ float srow[8][W_];

    const int w    = threadIdx.x >> 5;
    const int lane = threadIdx.x & 31;
    const int bh   = blockIdx.x * 8 + w;       // 0..8191
    const int b    = bh >> 9;
    const int h    = bh & 511;

    float* sr = srow[w];
    const unsigned short* grow = g_d + (size_t)bh * W_;
    #pragma unroll
    for (int j = 0; j < 16; ++j) {
        int y = lane + 32 * j;
        int dm = grow[y];
        sr[y] = (dm > 511) ? BIGF : (float)(dm * dm);
    }
    __syncwarp();

    float m = 0.0f;
    #pragma unroll 1
    for (int j = 0; j < 16; ++j) {
        int y = lane + 32 * j;
        float best = sr[y];
        for (int r = 1; r < W_; ++r) {
            float r2 = (float)(r * r);
            if (r2 >= best) break;             // exact early termination
            int jl = y - r, jr = y + r;
            if (jl >= 0)  best = fminf(best, sr[jl] + r2);
            if (jr < W_)  best = fminf(best, sr[jr] + r2);
        }
        if (h == b) g_rowsf[b * W_ + y] = best;
        m = fmaxf(m, best);
    }
    #pragma unroll
    for (int o = 16; o > 0; o >>= 1)
        m = fmaxf(m, __shfl_down_sync(0xffffffffu, m, o));
    if (lane == 0)
        atomicMax(&g_maxf[b], __float_as_int(m));
}

// ================= K3: fused weighted MSE + dice + finalize =================
// grid (MAIN_BX, B_), block 256; 4 float4 per thread. Targets from bitmask.
__global__ void __launch_bounds__(256)
k_main(const float4* __restrict__ in4, float* __restrict__ out, int out_size) {
    __shared__ float s_wb[W_];
    __shared__ float red[4][8];
    __shared__ bool  s_lastb;

    const int tid = threadIdx.x;
    const int b   = blockIdx.y;
    const float v = sqrtf(__int_as_float(g_maxf[b]));
    {
        s_wb[tid]       = v - sqrtf(g_rowsf[b * W_ + tid]);
        s_wb[tid + 256] = v - sqrtf(g_rowsf[b * W_ + tid + 256]);
    }
    __syncthreads();

    const size_t base4 = (size_t)b * (H_ * W_ / 4);
    const size_t basew = (size_t)b * (H_ * W_ / 32);
    const int q0 = blockIdx.x * 256 + tid;
    const float4* wb4 = (const float4*)s_wb;

    float sw = 0.f, sp = 0.f, st = 0.f, spt = 0.f;
    #pragma unroll
    for (int k = 0; k < 4; ++k) {
        int fi = q0 + k * (MAIN_BX * 256);
        float4 x = in4[base4 + fi];
        unsigned nib = (g_zmask[basew + (fi >> 3)] >> ((fi & 7) * 4)) & 0xFu;
        float4 wb = wb4[fi & 127];

        float px, wgt, dd, tt;
        tt = (nib & 1u) ? 0.f : 1.f;
        dd = x.x - tt; wgt = ((nib & 1u) ? 0.f : wb.x) + 0.001f; sw += wgt * dd * dd;
        px = __fdividef(1.f, 1.f + __expf(-x.x)); sp += px; st += tt; spt += px * tt;
        tt = (nib & 2u) ? 0.f : 1.f;
        dd = x.y - tt; wgt = ((nib & 2u) ? 0.f : wb.y) + 0.001f; sw += wgt * dd * dd;
        px = __fdividef(1.f, 1.f + __expf(-x.y)); sp += px; st += tt; spt += px * tt;
        tt = (nib & 4u) ? 0.f : 1.f;
        dd = x.z - tt; wgt = ((nib & 4u) ? 0.f : wb.z) + 0.001f; sw += wgt * dd * dd;
        px = __fdividef(1.f, 1.f + __expf(-x.z)); sp += px; st += tt; spt += px * tt;
        tt = (nib & 8u) ? 0.f : 1.f;
        dd = x.w - tt; wgt = ((nib & 8u) ? 0.f : wb.w) + 0.001f; sw += wgt * dd * dd;
        px = __fdividef(1.f, 1.f + __expf(-x.w)); sp += px; st += tt; spt += px * tt;
    }

    float vals[4] = {sw, sp, st, spt};
    #pragma unroll
    for (int q = 0; q < 4; ++q) {
        float s = vals[q];
        #pragma unroll
        for (int o = 16; o > 0; o >>= 1)
            s += __shfl_down_sync(0xffffffffu, s, o);
        if ((tid & 31) == 0) red[q][tid >> 5] = s;
    }
    __syncthreads();
    if (tid < 8) {
        #pragma unroll
        for (int q = 0; q < 4; ++q) {
            float s = red[q][tid];
            #pragma unroll
            for (int o = 4; o > 0; o >>= 1)
                s += __shfl_down_sync(0xffu, s, o);
            if (tid == 0)
                atomicAdd(&g_acc[q], (double)s);
        }
    }
    __syncthreads();

    if (tid == 0) {
        __threadfence();
        unsigned n = atomicAdd(&g_done, 1u);
        s_lastb = (n == MAIN_TOTAL - 1u);
    }
    __syncthreads();
    if (s_lastb && tid == 0) {
        double wmse = g_acc[0] / (double)NPIX;
        double P = g_acc[1], T = g_acc[2], I = g_acc[3];
        double dice = 1.0 - (2.0 * I + 1e-6) / (P + T + 1e-6);
        if (out_size >= 1) out[0] = (float)(0.6 * wmse);
        if (out_size >= 2) out[1] = (float)(1.0 * dice);
    }
}

// ---------------- launch ----------------
extern "C" void kernel_launch(void* const* d_in, const int* in_sizes, int n_in,
                              void* d_out, int out_size) {
    const float* inputs  = (const float*)d_in[0];
    const float* targets = (const float*)d_in[1];
    float* out = (float*)d_out;

    k_mask<<<NPIX / 32 / 256, 256>>>((const float4*)targets);
    dim3 gv(16, B_);
    k_vert<<<gv, 512>>>();
    k_row<<<B_ * H_ / 8, 256>>>();
    dim3 g3(MAIN_BX, B_);
    k_main<<<g3, 256>>>((const float4*)inputs, out, out_size);
}

// round 12
// speedup vs baseline: 1.1168x; 1.1168x over previous
#include <cuda_runtime.h>
#include <math.h>

#define B_    16
#define H_    512
#define W_    512
#define NPIX  (B_ * H_ * W_)
#define BIGF  100000000.0f
#define SENTI (1 << 28)
#define MAIN_BX 64
#define MAIN_TOTAL (MAIN_BX * B_)

// ---------------- scratch (device globals; no allocation) ----------------
__device__ unsigned short g_d[NPIX];            // vertical distance (0..511; >511 => BIG)
__device__ unsigned int   g_zmask[NPIX / 32];   // row-major zero bitmask of targets
__device__ float  g_rowsf[B_ * W_];             // f (squared) at h==b rows
__device__ int    g_maxf[B_];                   // per-batch max f (float bits)
__device__ double g_acc[4];                     // [wmse, sum_p, sum_t, sum_pt]
__device__ unsigned int g_done;

// ================= K1: vertical distances + zero bitmask (R6 exact) =================
// grid (16,16): 32-col group x batch. Block 512 = 16 warps; warp w: rows [32w,32w+32).
__global__ void __launch_bounds__(512, 2)
k_vert(const float* __restrict__ t) {
    __shared__ int s_first[16][32];
    __shared__ int s_last[16][32];
    __shared__ unsigned short sdn[32][512];   // backward distances

    const int lane = threadIdx.x & 31;
    const int w    = threadIdx.x >> 5;
    const int cg   = blockIdx.x;
    const int b    = blockIdx.y;
    const int col  = cg * 32 + lane;
    const int r0   = w * 32;

    if (blockIdx.x == 0 && blockIdx.y == 0) {
        if (threadIdx.x < B_) g_maxf[threadIdx.x] = 0;
        if (threadIdx.x < 4)  g_acc[threadIdx.x]  = 0.0;
        if (threadIdx.x == 31) g_done = 0u;
    }

    const float* tb = t + (size_t)b * H_ * W_;

    // load 32 rows; ballot -> row-major zero masks + column mask
    unsigned colmask = 0u, myrow = 0u;
    #pragma unroll
    for (int i = 0; i < 32; ++i) {
        float z = tb[(size_t)(r0 + i) * W_ + col];
        unsigned m = __ballot_sync(0xffffffffu, z == 0.0f);
        if (lane == i) myrow = m;
        colmask |= ((m >> lane) & 1u) << i;
    }
    g_zmask[((size_t)b * H_ + r0 + lane) * (W_ / 32) + cg] = myrow;

    s_last[w][lane]  = colmask ? (r0 + 31 - __clz(colmask)) : -SENTI;
    s_first[w][lane] = colmask ? (r0 + __ffs(colmask) - 1)  :  SENTI;
    __syncthreads();

    int lastAbove = -SENTI, nextBelow = SENTI;
    #pragma unroll
    for (int k = 0; k < 16; ++k) {
        int ll = s_last[k][lane];
        int ff = s_first[k][lane];
        if (k < w) lastAbove = max(lastAbove, ll);
        if (k > w) nextBelow = min(nextBelow, ff);
    }

    // backward pass -> shared
    {
        int d = min(nextBelow - (r0 + 32), 0x7FFE);
        #pragma unroll
        for (int i = 31; i >= 0; --i) {
            d = ((colmask >> i) & 1u) ? 0 : d + 1;
            sdn[i][threadIdx.x] = (unsigned short)d;
        }
    }
    // forward pass + emit
    unsigned short* gbase = g_d + (size_t)b * H_ * W_ + col;
    {
        int du = min((r0 - 1) - lastAbove, 0x7FFE);
        #pragma unroll
        for (int i = 0; i < 32; ++i) {
            du = ((colmask >> i) & 1u) ? 0 : du + 1;
            int dm = min(du, (int)sdn[i][threadIdx.x]);
            gbase[(size_t)(r0 + i) * W_] = (unsigned short)min(dm, 0x7FFF);
        }
    }
}

// ================= K2: row transform (warp per row) =================
// grid 1024, block 256 (8 warps -> 8 rows per block).
__global__ void __launch_bounds__(256)
k_row() {
    __shared__ float srow[8][W_];

    const int w    = threadIdx.x >> 5;
    const int lane = threadIdx.x & 31;
    const int bh   = blockIdx.x * 8 + w;       // 0..8191
    const int b    = bh >> 9;
    const int h    = bh & 511;

    float* sr = srow[w];
    const unsigned short* grow = g_d + (size_t)bh * W_;
    #pragma unroll
    for (int j = 0; j < 16; ++j) {
        int y = lane + 32 * j;
        int dm = grow[y];
        sr[y] = (dm > 511) ? BIGF : (float)(dm * dm);
    }
    __syncwarp();

    float m = 0.0f;
    #pragma unroll 1
    for (int j = 0; j < 16; ++j) {
        int y = lane + 32 * j;
        float best = sr[y];
        for (int r = 1; r < W_; ++r) {
            float r2 = (float)(r * r);
            if (r2 >= best) break;             // exact early termination
            int jl = y - r, jr = y + r;
            if (jl >= 0)  best = fminf(best, sr[jl] + r2);
            if (jr < W_)  best = fminf(best, sr[jr] + r2);
        }
        if (h == b) g_rowsf[b * W_ + y] = best;
        m = fmaxf(m, best);
    }
    #pragma unroll
    for (int o = 16; o > 0; o >>= 1)
        m = fmaxf(m, __shfl_down_sync(0xffffffffu, m, o));
    if (lane == 0)
        atomicMax(&g_maxf[b], __float_as_int(m));
}

// ================= K3: fused weighted MSE + dice + finalize =================
// grid (MAIN_BX, B_), block 256; all 8 loads hoisted for MLP.
__global__ void __launch_bounds__(256)
k_main(const float4* __restrict__ in4, float* __restrict__ out, int out_size) {
    __shared__ float s_wb[W_];
    __shared__ float red[4][8];
    __shared__ bool  s_lastb;

    const int tid = threadIdx.x;
    const int b   = blockIdx.y;
    const float v = sqrtf(__int_as_float(g_maxf[b]));
    {
        s_wb[tid]       = v - sqrtf(g_rowsf[b * W_ + tid]);
        s_wb[tid + 256] = v - sqrtf(g_rowsf[b * W_ + tid + 256]);
    }
    __syncthreads();

    const size_t base4 = (size_t)b * (H_ * W_ / 4);
    const size_t basew = (size_t)b * (H_ * W_ / 32);
    const int q0 = blockIdx.x * 256 + tid;
    const float4* wb4 = (const float4*)s_wb;

    // hoist all global loads (4 float4 + 4 mask words) -> MLP 8
    float4   x[4];
    unsigned mw[4];
    #pragma unroll
    for (int k = 0; k < 4; ++k) {
        int fi = q0 + k * (MAIN_BX * 256);
        x[k]  = in4[base4 + fi];
        mw[k] = g_zmask[basew + (fi >> 3)];
    }

    float sw = 0.f, sp = 0.f, st = 0.f, spt = 0.f;
    #pragma unroll
    for (int k = 0; k < 4; ++k) {
        int fi = q0 + k * (MAIN_BX * 256);
        unsigned nib = (mw[k] >> ((fi & 7) * 4)) & 0xFu;
        float4 wb = wb4[fi & 127];

        float px, wgt, dd, tt;
        tt = (nib & 1u) ? 0.f : 1.f;
        dd = x[k].x - tt; wgt = ((nib & 1u) ? 0.f : wb.x) + 0.001f; sw += wgt * dd * dd;
        px = __fdividef(1.f, 1.f + __expf(-x[k].x)); sp += px; st += tt; spt += px * tt;
        tt = (nib & 2u) ? 0.f : 1.f;
        dd = x[k].y - tt; wgt = ((nib & 2u) ? 0.f : wb.y) + 0.001f; sw += wgt * dd * dd;
        px = __fdividef(1.f, 1.f + __expf(-x[k].y)); sp += px; st += tt; spt += px * tt;
        tt = (nib & 4u) ? 0.f : 1.f;
        dd = x[k].z - tt; wgt = ((nib & 4u) ? 0.f : wb.z) + 0.001f; sw += wgt * dd * dd;
        px = __fdividef(1.f, 1.f + __expf(-x[k].z)); sp += px; st += tt; spt += px * tt;
        tt = (nib & 8u) ? 0.f : 1.f;
        dd = x[k].w - tt; wgt = ((nib & 8u) ? 0.f : wb.w) + 0.001f; sw += wgt * dd * dd;
        px = __fdividef(1.f, 1.f + __expf(-x[k].w)); sp += px; st += tt; spt += px * tt;
    }

    float vals[4] = {sw, sp, st, spt};
    #pragma unroll
    for (int q = 0; q < 4; ++q) {
        float s = vals[q];
        #pragma unroll
        for (int o = 16; o > 0; o >>= 1)
            s += __shfl_down_sync(0xffffffffu, s, o);
        if ((tid & 31) == 0) red[q][tid >> 5] = s;
    }
    __syncthreads();
    if (tid < 8) {
        #pragma unroll
        for (int q = 0; q < 4; ++q) {
            float s = red[q][tid];
            #pragma unroll
            for (int o = 4; o > 0; o >>= 1)
                s += __shfl_down_sync(0xffu, s, o);
            if (tid == 0)
                atomicAdd(&g_acc[q], (double)s);
        }
    }
    __syncthreads();

    if (tid == 0) {
        __threadfence();
        unsigned n = atomicAdd(&g_done, 1u);
        s_lastb = (n == MAIN_TOTAL - 1u);
    }
    __syncthreads();
    if (s_lastb && tid == 0) {
        double wmse = g_acc[0] / (double)NPIX;
        double P = g_acc[1], T = g_acc[2], I = g_acc[3];
        double dice = 1.0 - (2.0 * I + 1e-6) / (P + T + 1e-6);
        if (out_size >= 1) out[0] = (float)(0.6 * wmse);
        if (out_size >= 2) out[1] = (float)(1.0 * dice);
    }
}

// ---------------- launch ----------------
extern "C" void kernel_launch(void* const* d_in, const int* in_sizes, int n_in,
                              void* d_out, int out_size) {
    const float* inputs  = (const float*)d_in[0];
    const float* targets = (const float*)d_in[1];
    float* out = (float*)d_out;

    dim3 gv(16, B_);
    k_vert<<<gv, 512>>>(targets);
    k_row<<<B_ * H_ / 8, 256>>>();
    dim3 g3(MAIN_BX, B_);
    k_main<<<g3, 256>>>((const float4*)inputs, out, out_size);
}